// round 1
// baseline (speedup 1.0000x reference)
#include <cuda_runtime.h>
#include <math.h>

#define NPTS   524288
#define NLVL   16
#define TSIZE  (1 << 19)

// shared-memory parameter layout (floats)
#define OFF_W1 0        // [32,64]  2048
#define OFF_B1 2048     // [64]
#define OFF_W2 2112     // [64,16]  1024
#define OFF_B2 3136     // [16]
#define OFF_W3 3152     // [41,64]  2624
#define OFF_B3 5776     // [64]
#define OFF_W4 5840     // [64,64]  4096
#define OFF_B4 9936     // [64]
#define OFF_W5 10000    // [64,3]   192
#define OFF_B5 10192    // [3]
#define SMEM_TOTAL 10196

__global__ __launch_bounds__(256) void nerf_fused_kernel(
    const float* __restrict__ pos,      // [N,3]
    const float* __restrict__ dirv,     // [N,3]
    const float* __restrict__ tables,   // [L,T,F]
    const float* __restrict__ W1, const float* __restrict__ B1,
    const float* __restrict__ W2, const float* __restrict__ B2,
    const float* __restrict__ W3, const float* __restrict__ B3,
    const float* __restrict__ W4, const float* __restrict__ B4,
    const float* __restrict__ W5, const float* __restrict__ B5,
    float* __restrict__ out)            // [3N rgb][N sigma]
{
    __shared__ float s[SMEM_TOTAL];

    // cooperative parameter staging
    for (int t = threadIdx.x; t < 2048; t += 256) s[OFF_W1 + t] = W1[t];
    for (int t = threadIdx.x; t < 64;   t += 256) s[OFF_B1 + t] = B1[t];
    for (int t = threadIdx.x; t < 1024; t += 256) s[OFF_W2 + t] = W2[t];
    for (int t = threadIdx.x; t < 16;   t += 256) s[OFF_B2 + t] = B2[t];
    for (int t = threadIdx.x; t < 2624; t += 256) s[OFF_W3 + t] = W3[t];
    for (int t = threadIdx.x; t < 64;   t += 256) s[OFF_B3 + t] = B3[t];
    for (int t = threadIdx.x; t < 4096; t += 256) s[OFF_W4 + t] = W4[t];
    for (int t = threadIdx.x; t < 64;   t += 256) s[OFF_B4 + t] = B4[t];
    for (int t = threadIdx.x; t < 192;  t += 256) s[OFF_W5 + t] = W5[t];
    for (int t = threadIdx.x; t < 3;    t += 256) s[OFF_B5 + t] = B5[t];
    __syncthreads();

    const int i = blockIdx.x * 256 + threadIdx.x;
    if (i >= NPTS) return;

    // ---------------- hash grid encoding (32 features) ----------------
    const float px = pos[3 * i + 0];
    const float py = pos[3 * i + 1];
    const float pz = pos[3 * i + 2];

    float feat[32];
#pragma unroll
    for (int l = 0; l < NLVL; l++) {
        const float res = (float)(16 << l);      // exact: b == 2.0
        const float fx = px * res, fy = py * res, fz = pz * res;
        const float bx = floorf(fx), by = floorf(fy), bz = floorf(fz);
        const int ix = (int)bx, iy = (int)by, iz = (int)bz;
        const float wx = fx - bx, wy = fy - by, wz = fz - bz;
        const float2* __restrict__ tab =
            reinterpret_cast<const float2*>(tables) + (size_t)l * TSIZE;

        float f0 = 0.f, f1 = 0.f;
#pragma unroll
        for (int c = 0; c < 8; c++) {
            const int oi = (c >> 2) & 1, oj = (c >> 1) & 1, ok = c & 1;
            unsigned h = (unsigned)(ix + oi) * 1u
                       ^ (unsigned)(iy + oj) * 2654435761u
                       ^ (unsigned)(iz + ok) * 805459861u;
            h &= (TSIZE - 1);
            const float2 e = __ldg(tab + h);
            const float cw = (oi ? wx : 1.f - wx)
                           * (oj ? wy : 1.f - wy)
                           * (ok ? wz : 1.f - wz);
            f0 = fmaf(e.x, cw, f0);
            f1 = fmaf(e.y, cw, f1);
        }
        feat[2 * l + 0] = f0;
        feat[2 * l + 1] = f1;
    }

    // ---------------- density MLP: 32 -> 64 (relu) -> 16 ----------------
    float y[64];
    {
        const float4* __restrict__ Wv = reinterpret_cast<const float4*>(s + OFF_W1);
#pragma unroll
        for (int j = 0; j < 64; j++) y[j] = s[OFF_B1 + j];
#pragma unroll
        for (int k = 0; k < 32; k++) {
            const float v = feat[k];
#pragma unroll
            for (int j4 = 0; j4 < 16; j4++) {
                const float4 w = Wv[k * 16 + j4];
                y[4 * j4 + 0] = fmaf(v, w.x, y[4 * j4 + 0]);
                y[4 * j4 + 1] = fmaf(v, w.y, y[4 * j4 + 1]);
                y[4 * j4 + 2] = fmaf(v, w.z, y[4 * j4 + 2]);
                y[4 * j4 + 3] = fmaf(v, w.w, y[4 * j4 + 3]);
            }
        }
#pragma unroll
        for (int j = 0; j < 64; j++) y[j] = fmaxf(y[j], 0.f);
    }

    float den[16];
    {
        const float4* __restrict__ Wv = reinterpret_cast<const float4*>(s + OFF_W2);
#pragma unroll
        for (int j = 0; j < 16; j++) den[j] = s[OFF_B2 + j];
#pragma unroll
        for (int k = 0; k < 64; k++) {
            const float v = y[k];
#pragma unroll
            for (int j4 = 0; j4 < 4; j4++) {
                const float4 w = Wv[k * 4 + j4];
                den[4 * j4 + 0] = fmaf(v, w.x, den[4 * j4 + 0]);
                den[4 * j4 + 1] = fmaf(v, w.y, den[4 * j4 + 1]);
                den[4 * j4 + 2] = fmaf(v, w.z, den[4 * j4 + 2]);
                den[4 * j4 + 3] = fmaf(v, w.w, den[4 * j4 + 3]);
            }
        }
    }
    const float sigma = fmaxf(den[15], 0.f);

    // ---------------- SH degree-4 encoding (25) ----------------
    float sh[25];
    {
        const float x = dirv[3 * i + 0];
        const float yv = dirv[3 * i + 1];
        const float z = dirv[3 * i + 2];
        const float x2 = x * x, y2 = yv * yv, z2 = z * z;
        const float xy = x * yv, xz = x * z, yz = yv * z;
        const float x4 = x2 * x2, y4 = y2 * y2;

        sh[0] = 0.28209479177387814f;
        const float c1 = 0.4886025119029199f;
        sh[1] = -c1 * yv;
        sh[2] =  c1 * z;
        sh[3] = -c1 * x;
        const float sub = 0.31539156525252005f;
        const float v1 = 0.5462742152960396f;
        const float v2 = 1.0925484305920792f;
        const float v3 = 0.9461746957575601f;
        sh[4] =  v2 * xy;
        sh[5] = -v2 * yz;
        sh[6] =  v3 * z2 - sub;
        sh[7] = -v2 * xz;
        sh[8] =  v1 * x2 - v1 * y2;
        const float w1 = 1.445305721320277f;
        const float w2 = 2.890611442640554f;
        const float w3 = 0.5900435899266435f;
        const float w4 = 0.304697199642977f;
        sh[9]  = -w3 * yv * (3.0f * x2 - y2);
        sh[10] =  w2 * xy * z;
        sh[11] =  w4 * yv * (1.5f - 7.5f * z2);
        sh[12] =  1.24392110863372f * z * (1.5f * z2 - 0.5f) - 0.497568443453487f * z;
        sh[13] =  w4 * x * (1.5f - 7.5f * z2);
        sh[14] =  w1 * z * (x2 - y2);
        sh[15] = -w3 * x * (x2 - 3.0f * y2);
        sh[16] =  2.5033429417967f * xy * (x2 - y2);
        sh[17] = -1.77013076977993f * yz * (3.0f * x2 - y2);
        sh[18] =  0.126156626101008f * xy * (52.5f * z2 - 7.5f);
        sh[19] =  0.267618617422916f * yv * (2.33333333333333f * z * (1.5f - 7.5f * z2) + 4.0f * z);
        sh[20] =  1.48099765681286f * z * (1.66666666666667f * z * (1.5f * z2 - 0.5f)
                                           - 0.666666666666667f * z)
                  - 0.952069922236839f * z2 + 0.317356640745613f;
        sh[21] =  0.267618617422916f * x * (2.33333333333333f * z * (1.5f - 7.5f * z2) + 4.0f * z);
        sh[22] =  0.063078313050504f * (x2 - y2) * (52.5f * z2 - 7.5f);
        sh[23] = -1.77013076977993f * xz * (x2 - 3.0f * y2);
        sh[24] = -3.75501441269506f * x2 * y2 + 0.625835735449176f * x4 + 0.625835735449176f * y4;
    }

    // ---------------- color MLP: 41 -> 64 (relu) ----------------
    float h1[64];
    {
        const float4* __restrict__ Wv = reinterpret_cast<const float4*>(s + OFF_W3);
#pragma unroll
        for (int j = 0; j < 64; j++) h1[j] = s[OFF_B3 + j];
#pragma unroll
        for (int k = 0; k < 41; k++) {
            const float v = (k < 16) ? den[k] : sh[k - 16];
#pragma unroll
            for (int j4 = 0; j4 < 16; j4++) {
                const float4 w = Wv[k * 16 + j4];
                h1[4 * j4 + 0] = fmaf(v, w.x, h1[4 * j4 + 0]);
                h1[4 * j4 + 1] = fmaf(v, w.y, h1[4 * j4 + 1]);
                h1[4 * j4 + 2] = fmaf(v, w.z, h1[4 * j4 + 2]);
                h1[4 * j4 + 3] = fmaf(v, w.w, h1[4 * j4 + 3]);
            }
        }
#pragma unroll
        for (int j = 0; j < 64; j++) h1[j] = fmaxf(h1[j], 0.f);
    }

    // ---------------- color MLP: 64 -> 64 (relu) ----------------
    float h2[64];
    {
        const float4* __restrict__ Wv = reinterpret_cast<const float4*>(s + OFF_W4);
#pragma unroll
        for (int j = 0; j < 64; j++) h2[j] = s[OFF_B4 + j];
#pragma unroll
        for (int k = 0; k < 64; k++) {
            const float v = h1[k];
#pragma unroll
            for (int j4 = 0; j4 < 16; j4++) {
                const float4 w = Wv[k * 16 + j4];
                h2[4 * j4 + 0] = fmaf(v, w.x, h2[4 * j4 + 0]);
                h2[4 * j4 + 1] = fmaf(v, w.y, h2[4 * j4 + 1]);
                h2[4 * j4 + 2] = fmaf(v, w.z, h2[4 * j4 + 2]);
                h2[4 * j4 + 3] = fmaf(v, w.w, h2[4 * j4 + 3]);
            }
        }
#pragma unroll
        for (int j = 0; j < 64; j++) h2[j] = fmaxf(h2[j], 0.f);
    }

    // ---------------- color head: 64 -> 3, sigmoid ----------------
    float r0 = s[OFF_B5 + 0], r1 = s[OFF_B5 + 1], r2 = s[OFF_B5 + 2];
#pragma unroll
    for (int k = 0; k < 64; k++) {
        const float v = h2[k];
        r0 = fmaf(v, s[OFF_W5 + k * 3 + 0], r0);
        r1 = fmaf(v, s[OFF_W5 + k * 3 + 1], r1);
        r2 = fmaf(v, s[OFF_W5 + k * 3 + 2], r2);
    }
    r0 = 1.0f / (1.0f + expf(-r0));
    r1 = 1.0f / (1.0f + expf(-r1));
    r2 = 1.0f / (1.0f + expf(-r2));

    out[3 * i + 0] = r0;
    out[3 * i + 1] = r1;
    out[3 * i + 2] = r2;
    out[3 * NPTS + i] = sigma;
}

extern "C" void kernel_launch(void* const* d_in, const int* in_sizes, int n_in,
                              void* d_out, int out_size)
{
    const float* pos    = (const float*)d_in[0];
    const float* dirv   = (const float*)d_in[1];
    const float* tables = (const float*)d_in[2];
    const float* W1 = (const float*)d_in[3];
    const float* B1 = (const float*)d_in[4];
    const float* W2 = (const float*)d_in[5];
    const float* B2 = (const float*)d_in[6];
    const float* W3 = (const float*)d_in[7];
    const float* B3 = (const float*)d_in[8];
    const float* W4 = (const float*)d_in[9];
    const float* B4 = (const float*)d_in[10];
    const float* W5 = (const float*)d_in[11];
    const float* B5 = (const float*)d_in[12];
    float* out = (float*)d_out;

    nerf_fused_kernel<<<NPTS / 256, 256>>>(
        pos, dirv, tables,
        W1, B1, W2, B2, W3, B3, W4, B4, W5, B5, out);
}

// round 2
// speedup vs baseline: 1.6380x; 1.6380x over previous
#include <cuda_runtime.h>
#include <math.h>

#define NPTS   524288
#define NLVL   16
#define TSIZE  (1 << 19)

// shared-memory parameter layout (floats)
#define OFF_W1 0        // [32,64]  2048
#define OFF_B1 2048     // [64]
#define OFF_W2 2112     // [64,16]  1024
#define OFF_B2 3136     // [16]
#define OFF_W3 3152     // [41,64]  2624
#define OFF_B3 5776     // [64]
#define OFF_W4 5840     // [64,64]  4096
#define OFF_B4 9936     // [64]
#define OFF_W5 10000    // [64,3]   192
#define OFF_B5 10192    // [3]
#define SMEM_TOTAL 10196

__global__ __launch_bounds__(256, 2) void nerf_fused_kernel(
    const float* __restrict__ pos,      // [N,3]
    const float* __restrict__ dirv,     // [N,3]
    const float* __restrict__ tables,   // [L,T,F]
    const float* __restrict__ W1, const float* __restrict__ B1,
    const float* __restrict__ W2, const float* __restrict__ B2,
    const float* __restrict__ W3, const float* __restrict__ B3,
    const float* __restrict__ W4, const float* __restrict__ B4,
    const float* __restrict__ W5, const float* __restrict__ B5,
    float* __restrict__ out)            // [3N rgb][N sigma]
{
    __shared__ float s[SMEM_TOTAL];

    // cooperative parameter staging
    for (int t = threadIdx.x; t < 2048; t += 256) s[OFF_W1 + t] = W1[t];
    for (int t = threadIdx.x; t < 64;   t += 256) s[OFF_B1 + t] = B1[t];
    for (int t = threadIdx.x; t < 1024; t += 256) s[OFF_W2 + t] = W2[t];
    for (int t = threadIdx.x; t < 16;   t += 256) s[OFF_B2 + t] = B2[t];
    for (int t = threadIdx.x; t < 2624; t += 256) s[OFF_W3 + t] = W3[t];
    for (int t = threadIdx.x; t < 64;   t += 256) s[OFF_B3 + t] = B3[t];
    for (int t = threadIdx.x; t < 4096; t += 256) s[OFF_W4 + t] = W4[t];
    for (int t = threadIdx.x; t < 64;   t += 256) s[OFF_B4 + t] = B4[t];
    for (int t = threadIdx.x; t < 192;  t += 256) s[OFF_W5 + t] = W5[t];
    for (int t = threadIdx.x; t < 3;    t += 256) s[OFF_B5 + t] = B5[t];
    __syncthreads();

    const int i = blockIdx.x * 256 + threadIdx.x;

    // ---------------- hash grid encoding (32 features) ----------------
    const float px = pos[3 * i + 0];
    const float py = pos[3 * i + 1];
    const float pz = pos[3 * i + 2];

    float feat[32];
#pragma unroll
    for (int l = 0; l < NLVL; l++) {
        const float res = (float)(16 << l);      // exact: growth factor b == 2.0
        const float fx = px * res, fy = py * res, fz = pz * res;
        const float bx = floorf(fx), by = floorf(fy), bz = floorf(fz);
        const int ix = (int)bx, iy = (int)by, iz = (int)bz;
        const float wx = fx - bx, wy = fy - by, wz = fz - bz;
        const float2* __restrict__ tab =
            reinterpret_cast<const float2*>(tables) + (size_t)l * TSIZE;

        float f0 = 0.f, f1 = 0.f;
#pragma unroll
        for (int c = 0; c < 8; c++) {
            const int oi = (c >> 2) & 1, oj = (c >> 1) & 1, ok = c & 1;
            unsigned h = (unsigned)(ix + oi) * 1u
                       ^ (unsigned)(iy + oj) * 2654435761u
                       ^ (unsigned)(iz + ok) * 805459861u;
            h &= (TSIZE - 1);
            const float2 e = __ldg(tab + h);
            const float cw = (oi ? wx : 1.f - wx)
                           * (oj ? wy : 1.f - wy)
                           * (ok ? wz : 1.f - wz);
            f0 = fmaf(e.x, cw, f0);
            f1 = fmaf(e.y, cw, f1);
        }
        feat[2 * l + 0] = f0;
        feat[2 * l + 1] = f1;
    }

    // ------- density MLP: 32 -> 64 (relu) -> 16, y chunked (never fully live) -------
    float den[16];
#pragma unroll
    for (int j = 0; j < 16; j++) den[j] = s[OFF_B2 + j];

    {
        const float4* __restrict__ W1v = reinterpret_cast<const float4*>(s + OFF_W1);
        const float4* __restrict__ W2v = reinterpret_cast<const float4*>(s + OFF_W2);
#pragma unroll
        for (int cch = 0; cch < 4; cch++) {         // y chunk = hidden units [16c,16c+16)
            float yc[16];
#pragma unroll
            for (int j = 0; j < 16; j++) yc[j] = s[OFF_B1 + cch * 16 + j];
#pragma unroll
            for (int k = 0; k < 32; k++) {
                const float v = feat[k];
#pragma unroll
                for (int j4 = 0; j4 < 4; j4++) {
                    const float4 w = W1v[k * 16 + cch * 4 + j4];
                    yc[4 * j4 + 0] = fmaf(v, w.x, yc[4 * j4 + 0]);
                    yc[4 * j4 + 1] = fmaf(v, w.y, yc[4 * j4 + 1]);
                    yc[4 * j4 + 2] = fmaf(v, w.z, yc[4 * j4 + 2]);
                    yc[4 * j4 + 3] = fmaf(v, w.w, yc[4 * j4 + 3]);
                }
            }
#pragma unroll
            for (int k = 0; k < 16; k++) {
                const float v = fmaxf(yc[k], 0.f);
#pragma unroll
                for (int j4 = 0; j4 < 4; j4++) {
                    const float4 w = W2v[(cch * 16 + k) * 4 + j4];
                    den[4 * j4 + 0] = fmaf(v, w.x, den[4 * j4 + 0]);
                    den[4 * j4 + 1] = fmaf(v, w.y, den[4 * j4 + 1]);
                    den[4 * j4 + 2] = fmaf(v, w.z, den[4 * j4 + 2]);
                    den[4 * j4 + 3] = fmaf(v, w.w, den[4 * j4 + 3]);
                }
            }
        }
    }
    const float sigma = fmaxf(den[15], 0.f);
    out[3 * NPTS + i] = sigma;

    // ---------------- SH degree-4 encoding (25) ----------------
    float sh[25];
    {
        const float x = dirv[3 * i + 0];
        const float yv = dirv[3 * i + 1];
        const float z = dirv[3 * i + 2];
        const float x2 = x * x, y2 = yv * yv, z2 = z * z;
        const float xy = x * yv, xz = x * z, yz = yv * z;
        const float x4 = x2 * x2, y4 = y2 * y2;

        sh[0] = 0.28209479177387814f;
        const float c1 = 0.4886025119029199f;
        sh[1] = -c1 * yv;
        sh[2] =  c1 * z;
        sh[3] = -c1 * x;
        const float sub = 0.31539156525252005f;
        const float v1 = 0.5462742152960396f;
        const float v2 = 1.0925484305920792f;
        const float v3 = 0.9461746957575601f;
        sh[4] =  v2 * xy;
        sh[5] = -v2 * yz;
        sh[6] =  v3 * z2 - sub;
        sh[7] = -v2 * xz;
        sh[8] =  v1 * x2 - v1 * y2;
        const float w1 = 1.445305721320277f;
        const float w2 = 2.890611442640554f;
        const float w3 = 0.5900435899266435f;
        const float w4 = 0.304697199642977f;
        sh[9]  = -w3 * yv * (3.0f * x2 - y2);
        sh[10] =  w2 * xy * z;
        sh[11] =  w4 * yv * (1.5f - 7.5f * z2);
        sh[12] =  1.24392110863372f * z * (1.5f * z2 - 0.5f) - 0.497568443453487f * z;
        sh[13] =  w4 * x * (1.5f - 7.5f * z2);
        sh[14] =  w1 * z * (x2 - y2);
        sh[15] = -w3 * x * (x2 - 3.0f * y2);
        sh[16] =  2.5033429417967f * xy * (x2 - y2);
        sh[17] = -1.77013076977993f * yz * (3.0f * x2 - y2);
        sh[18] =  0.126156626101008f * xy * (52.5f * z2 - 7.5f);
        sh[19] =  0.267618617422916f * yv * (2.33333333333333f * z * (1.5f - 7.5f * z2) + 4.0f * z);
        sh[20] =  1.48099765681286f * z * (1.66666666666667f * z * (1.5f * z2 - 0.5f)
                                           - 0.666666666666667f * z)
                  - 0.952069922236839f * z2 + 0.317356640745613f;
        sh[21] =  0.267618617422916f * x * (2.33333333333333f * z * (1.5f - 7.5f * z2) + 4.0f * z);
        sh[22] =  0.063078313050504f * (x2 - y2) * (52.5f * z2 - 7.5f);
        sh[23] = -1.77013076977993f * xz * (x2 - 3.0f * y2);
        sh[24] = -3.75501441269506f * x2 * y2 + 0.625835735449176f * x4 + 0.625835735449176f * y4;
    }

    // ---------------- color MLP layer 1: 41 -> 64 (relu), full h1 ----------------
    float h1[64];
    {
        const float4* __restrict__ Wv = reinterpret_cast<const float4*>(s + OFF_W3);
#pragma unroll
        for (int j = 0; j < 64; j++) h1[j] = s[OFF_B3 + j];
#pragma unroll
        for (int k = 0; k < 41; k++) {
            const float v = (k < 16) ? den[k] : sh[k - 16];
#pragma unroll
            for (int j4 = 0; j4 < 16; j4++) {
                const float4 w = Wv[k * 16 + j4];
                h1[4 * j4 + 0] = fmaf(v, w.x, h1[4 * j4 + 0]);
                h1[4 * j4 + 1] = fmaf(v, w.y, h1[4 * j4 + 1]);
                h1[4 * j4 + 2] = fmaf(v, w.z, h1[4 * j4 + 2]);
                h1[4 * j4 + 3] = fmaf(v, w.w, h1[4 * j4 + 3]);
            }
        }
#pragma unroll
        for (int j = 0; j < 64; j++) h1[j] = fmaxf(h1[j], 0.f);
    }

    // ------- color MLP layer 2 + head: h2 chunked, folded into rgb accumulators -------
    float r0 = s[OFF_B5 + 0], r1 = s[OFF_B5 + 1], r2 = s[OFF_B5 + 2];
    {
        const float4* __restrict__ W4v = reinterpret_cast<const float4*>(s + OFF_W4);
#pragma unroll
        for (int cch = 0; cch < 4; cch++) {         // h2 outputs [16c,16c+16)
            float hc[16];
#pragma unroll
            for (int j = 0; j < 16; j++) hc[j] = s[OFF_B4 + cch * 16 + j];
#pragma unroll
            for (int k = 0; k < 64; k++) {
                const float v = h1[k];
#pragma unroll
                for (int j4 = 0; j4 < 4; j4++) {
                    const float4 w = W4v[k * 16 + cch * 4 + j4];
                    hc[4 * j4 + 0] = fmaf(v, w.x, hc[4 * j4 + 0]);
                    hc[4 * j4 + 1] = fmaf(v, w.y, hc[4 * j4 + 1]);
                    hc[4 * j4 + 2] = fmaf(v, w.z, hc[4 * j4 + 2]);
                    hc[4 * j4 + 3] = fmaf(v, w.w, hc[4 * j4 + 3]);
                }
            }
#pragma unroll
            for (int k = 0; k < 16; k++) {
                const float v = fmaxf(hc[k], 0.f);
                const int kk = cch * 16 + k;
                r0 = fmaf(v, s[OFF_W5 + kk * 3 + 0], r0);
                r1 = fmaf(v, s[OFF_W5 + kk * 3 + 1], r1);
                r2 = fmaf(v, s[OFF_W5 + kk * 3 + 2], r2);
            }
        }
    }

    r0 = 1.0f / (1.0f + expf(-r0));
    r1 = 1.0f / (1.0f + expf(-r1));
    r2 = 1.0f / (1.0f + expf(-r2));

    out[3 * i + 0] = r0;
    out[3 * i + 1] = r1;
    out[3 * i + 2] = r2;
}

extern "C" void kernel_launch(void* const* d_in, const int* in_sizes, int n_in,
                              void* d_out, int out_size)
{
    const float* pos    = (const float*)d_in[0];
    const float* dirv   = (const float*)d_in[1];
    const float* tables = (const float*)d_in[2];
    const float* W1 = (const float*)d_in[3];
    const float* B1 = (const float*)d_in[4];
    const float* W2 = (const float*)d_in[5];
    const float* B2 = (const float*)d_in[6];
    const float* W3 = (const float*)d_in[7];
    const float* B3 = (const float*)d_in[8];
    const float* W4 = (const float*)d_in[9];
    const float* B4 = (const float*)d_in[10];
    const float* W5 = (const float*)d_in[11];
    const float* B5 = (const float*)d_in[12];
    float* out = (float*)d_out;

    nerf_fused_kernel<<<NPTS / 256, 256>>>(
        pos, dirv, tables,
        W1, B1, W2, B2, W3, B3, W4, B4, W5, B5, out);
}

// round 4
// speedup vs baseline: 2.2028x; 1.3448x over previous
#include <cuda_runtime.h>
#include <math.h>

#define NPTS   524288
#define NLVL   16
#define TSIZE  (1 << 19)

// shared-memory parameter layout (floats)
#define OFF_W1 0        // [32,64]  2048
#define OFF_B1 2048     // [64]
#define OFF_W2 2112     // [64,16]  1024
#define OFF_B2 3136     // [16]
#define OFF_W3 3152     // [41,64]  2624
#define OFF_B3 5776     // [64]
#define OFF_W4 5840     // [64,64]  4096
#define OFF_B4 9936     // [64]
#define OFF_W5 10000    // [64,3]   192
#define OFF_B5 10192    // [3]
#define SMEM_TOTAL 10196

// packed f32x2 helpers (FFMA2 is only reachable via PTX on sm_103a)
#define FMA2(d, a, b, c) \
    asm("fma.rn.f32x2 %0, %1, %2, %3;" : "=l"(d) : "l"(a), "l"(b), "l"(c))
#define PACK2(d, lo, hi) \
    asm("mov.b64 %0, {%1, %2};" : "=l"(d) : "f"(lo), "f"(hi))
#define UNPACK2(lo, hi, v) \
    asm("mov.b64 {%0, %1}, %2;" : "=f"(lo), "=f"(hi) : "l"(v))

typedef unsigned long long u64;

__global__ __launch_bounds__(256, 2) void nerf_fused_kernel(
    const float* __restrict__ pos,      // [N,3]
    const float* __restrict__ dirv,     // [N,3]
    const float* __restrict__ tables,   // [L,T,F]
    const float* __restrict__ W1, const float* __restrict__ B1,
    const float* __restrict__ W2, const float* __restrict__ B2,
    const float* __restrict__ W3, const float* __restrict__ B3,
    const float* __restrict__ W4, const float* __restrict__ B4,
    const float* __restrict__ W5, const float* __restrict__ B5,
    float* __restrict__ out)            // [3N rgb][N sigma]
{
    __shared__ float s[SMEM_TOTAL];

    for (int t = threadIdx.x; t < 2048; t += 256) s[OFF_W1 + t] = W1[t];
    for (int t = threadIdx.x; t < 64;   t += 256) s[OFF_B1 + t] = B1[t];
    for (int t = threadIdx.x; t < 1024; t += 256) s[OFF_W2 + t] = W2[t];
    for (int t = threadIdx.x; t < 16;   t += 256) s[OFF_B2 + t] = B2[t];
    for (int t = threadIdx.x; t < 2624; t += 256) s[OFF_W3 + t] = W3[t];
    for (int t = threadIdx.x; t < 64;   t += 256) s[OFF_B3 + t] = B3[t];
    for (int t = threadIdx.x; t < 4096; t += 256) s[OFF_W4 + t] = W4[t];
    for (int t = threadIdx.x; t < 64;   t += 256) s[OFF_B4 + t] = B4[t];
    for (int t = threadIdx.x; t < 192;  t += 256) s[OFF_W5 + t] = W5[t];
    for (int t = threadIdx.x; t < 3;    t += 256) s[OFF_B5 + t] = B5[t];
    __syncthreads();

    const int i = blockIdx.x * 256 + threadIdx.x;

    // ---------------- hash grid encoding (32 features) ----------------
    const float px = pos[3 * i + 0];
    const float py = pos[3 * i + 1];
    const float pz = pos[3 * i + 2];

    float feat[32];
#pragma unroll
    for (int l = 0; l < NLVL; l++) {
        const float res = (float)(16 << l);      // exact: growth factor b == 2.0
        const float fx = px * res, fy = py * res, fz = pz * res;
        const float bx = floorf(fx), by = floorf(fy), bz = floorf(fz);
        const int ix = (int)bx, iy = (int)by, iz = (int)bz;
        const float wx = fx - bx, wy = fy - by, wz = fz - bz;
        const float2* __restrict__ tab =
            reinterpret_cast<const float2*>(tables) + (size_t)l * TSIZE;

        float f0 = 0.f, f1 = 0.f;
#pragma unroll
        for (int c = 0; c < 8; c++) {
            const int oi = (c >> 2) & 1, oj = (c >> 1) & 1, ok = c & 1;
            unsigned h = (unsigned)(ix + oi) * 1u
                       ^ (unsigned)(iy + oj) * 2654435761u
                       ^ (unsigned)(iz + ok) * 805459861u;
            h &= (TSIZE - 1);
            const float2 e = __ldg(tab + h);
            const float cw = (oi ? wx : 1.f - wx)
                           * (oj ? wy : 1.f - wy)
                           * (ok ? wz : 1.f - wz);
            f0 = fmaf(e.x, cw, f0);
            f1 = fmaf(e.y, cw, f1);
        }
        feat[2 * l + 0] = f0;
        feat[2 * l + 1] = f1;
    }

    // ------- density MLP: 32 -> 64 (relu) -> 16, packed f32x2 -------
    u64 den[8];
#pragma unroll
    for (int j = 0; j < 8; j++) PACK2(den[j], s[OFF_B2 + 2 * j], s[OFF_B2 + 2 * j + 1]);

    {
        const ulonglong2* __restrict__ W1v = reinterpret_cast<const ulonglong2*>(s + OFF_W1);
        const ulonglong2* __restrict__ W2v = reinterpret_cast<const ulonglong2*>(s + OFF_W2);
#pragma unroll
        for (int cch = 0; cch < 4; cch++) {         // hidden units [16c,16c+16)
            u64 yc[8];
#pragma unroll
            for (int j = 0; j < 8; j++)
                PACK2(yc[j], s[OFF_B1 + cch * 16 + 2 * j], s[OFF_B1 + cch * 16 + 2 * j + 1]);
#pragma unroll
            for (int k = 0; k < 32; k++) {
                u64 vv; PACK2(vv, feat[k], feat[k]);
#pragma unroll
                for (int j2 = 0; j2 < 4; j2++) {
                    const ulonglong2 w = W1v[k * 16 + cch * 4 + j2];
                    FMA2(yc[2 * j2 + 0], vv, w.x, yc[2 * j2 + 0]);
                    FMA2(yc[2 * j2 + 1], vv, w.y, yc[2 * j2 + 1]);
                }
            }
            // fold relu(yc) into den via W2 rows (each row: 16 floats = 4 ulonglong2)
#pragma unroll
            for (int k2 = 0; k2 < 8; k2++) {
                float a, b; UNPACK2(a, b, yc[k2]);
                a = fmaxf(a, 0.f); b = fmaxf(b, 0.f);
                u64 va; PACK2(va, a, a);
                u64 vb; PACK2(vb, b, b);
                const int kk = cch * 16 + 2 * k2;
#pragma unroll
                for (int j2 = 0; j2 < 4; j2++) {
                    const ulonglong2 wa = W2v[kk * 4 + j2];
                    FMA2(den[2 * j2 + 0], va, wa.x, den[2 * j2 + 0]);
                    FMA2(den[2 * j2 + 1], va, wa.y, den[2 * j2 + 1]);
                }
#pragma unroll
                for (int j2 = 0; j2 < 4; j2++) {
                    const ulonglong2 wb = W2v[(kk + 1) * 4 + j2];
                    FMA2(den[2 * j2 + 0], vb, wb.x, den[2 * j2 + 0]);
                    FMA2(den[2 * j2 + 1], vb, wb.y, den[2 * j2 + 1]);
                }
            }
        }
    }

    float den_s[16];
#pragma unroll
    for (int j = 0; j < 8; j++) UNPACK2(den_s[2 * j], den_s[2 * j + 1], den[j]);
    out[3 * NPTS + i] = fmaxf(den_s[15], 0.f);

    // ---------------- SH degree-4 encoding (25) ----------------
    float sh[25];
    {
        const float x = dirv[3 * i + 0];
        const float yv = dirv[3 * i + 1];
        const float z = dirv[3 * i + 2];
        const float x2 = x * x, y2 = yv * yv, z2 = z * z;
        const float xy = x * yv, xz = x * z, yz = yv * z;
        const float x4 = x2 * x2, y4 = y2 * y2;

        sh[0] = 0.28209479177387814f;
        const float c1 = 0.4886025119029199f;
        sh[1] = -c1 * yv;
        sh[2] =  c1 * z;
        sh[3] = -c1 * x;
        const float sub = 0.31539156525252005f;
        const float v1 = 0.5462742152960396f;
        const float v2 = 1.0925484305920792f;
        const float v3 = 0.9461746957575601f;
        sh[4] =  v2 * xy;
        sh[5] = -v2 * yz;
        sh[6] =  v3 * z2 - sub;
        sh[7] = -v2 * xz;
        sh[8] =  v1 * x2 - v1 * y2;
        const float w1 = 1.445305721320277f;
        const float w2 = 2.890611442640554f;
        const float w3 = 0.5900435899266435f;
        const float w4 = 0.304697199642977f;
        sh[9]  = -w3 * yv * (3.0f * x2 - y2);
        sh[10] =  w2 * xy * z;
        sh[11] =  w4 * yv * (1.5f - 7.5f * z2);
        sh[12] =  1.24392110863372f * z * (1.5f * z2 - 0.5f) - 0.497568443453487f * z;
        sh[13] =  w4 * x * (1.5f - 7.5f * z2);
        sh[14] =  w1 * z * (x2 - y2);
        sh[15] = -w3 * x * (x2 - 3.0f * y2);
        sh[16] =  2.5033429417967f * xy * (x2 - y2);
        sh[17] = -1.77013076977993f * yz * (3.0f * x2 - y2);
        sh[18] =  0.126156626101008f * xy * (52.5f * z2 - 7.5f);
        sh[19] =  0.267618617422916f * yv * (2.33333333333333f * z * (1.5f - 7.5f * z2) + 4.0f * z);
        sh[20] =  1.48099765681286f * z * (1.66666666666667f * z * (1.5f * z2 - 0.5f)
                                           - 0.666666666666667f * z)
                  - 0.952069922236839f * z2 + 0.317356640745613f;
        sh[21] =  0.267618617422916f * x * (2.33333333333333f * z * (1.5f - 7.5f * z2) + 4.0f * z);
        sh[22] =  0.063078313050504f * (x2 - y2) * (52.5f * z2 - 7.5f);
        sh[23] = -1.77013076977993f * xz * (x2 - 3.0f * y2);
        sh[24] = -3.75501441269506f * x2 * y2 + 0.625835735449176f * x4 + 0.625835735449176f * y4;
    }

    // ---------------- color MLP layer 1: 41 -> 64 (relu), packed ----------------
    u64 h1[32];
    {
        const ulonglong2* __restrict__ Wv = reinterpret_cast<const ulonglong2*>(s + OFF_W3);
#pragma unroll
        for (int j = 0; j < 32; j++)
            PACK2(h1[j], s[OFF_B3 + 2 * j], s[OFF_B3 + 2 * j + 1]);
#pragma unroll
        for (int k = 0; k < 41; k++) {
            const float v = (k < 16) ? den_s[k] : sh[k - 16];
            u64 vv; PACK2(vv, v, v);
#pragma unroll
            for (int j2 = 0; j2 < 16; j2++) {
                const ulonglong2 w = Wv[k * 16 + j2];
                FMA2(h1[2 * j2 + 0], vv, w.x, h1[2 * j2 + 0]);
                FMA2(h1[2 * j2 + 1], vv, w.y, h1[2 * j2 + 1]);
            }
        }
    }

    float h1s[64];
#pragma unroll
    for (int j = 0; j < 32; j++) {
        float a, b; UNPACK2(a, b, h1[j]);
        h1s[2 * j]     = fmaxf(a, 0.f);
        h1s[2 * j + 1] = fmaxf(b, 0.f);
    }

    // ------- color MLP layer 2 + head: h2 chunked, packed, folded into rgb -------
    float r0 = s[OFF_B5 + 0], r1 = s[OFF_B5 + 1], r2 = s[OFF_B5 + 2];
    {
        const ulonglong2* __restrict__ W4v = reinterpret_cast<const ulonglong2*>(s + OFF_W4);
#pragma unroll
        for (int cch = 0; cch < 4; cch++) {         // h2 outputs [16c,16c+16)
            u64 hc[8];
#pragma unroll
            for (int j = 0; j < 8; j++)
                PACK2(hc[j], s[OFF_B4 + cch * 16 + 2 * j], s[OFF_B4 + cch * 16 + 2 * j + 1]);
#pragma unroll
            for (int k = 0; k < 64; k++) {
                u64 vv; PACK2(vv, h1s[k], h1s[k]);
#pragma unroll
                for (int j2 = 0; j2 < 4; j2++) {
                    const ulonglong2 w = W4v[k * 16 + cch * 4 + j2];
                    FMA2(hc[2 * j2 + 0], vv, w.x, hc[2 * j2 + 0]);
                    FMA2(hc[2 * j2 + 1], vv, w.y, hc[2 * j2 + 1]);
                }
            }
#pragma unroll
            for (int k2 = 0; k2 < 8; k2++) {
                float a, b; UNPACK2(a, b, hc[k2]);
                a = fmaxf(a, 0.f); b = fmaxf(b, 0.f);
                const int kk = cch * 16 + 2 * k2;
                r0 = fmaf(a, s[OFF_W5 + kk * 3 + 0], r0);
                r1 = fmaf(a, s[OFF_W5 + kk * 3 + 1], r1);
                r2 = fmaf(a, s[OFF_W5 + kk * 3 + 2], r2);
                r0 = fmaf(b, s[OFF_W5 + (kk + 1) * 3 + 0], r0);
                r1 = fmaf(b, s[OFF_W5 + (kk + 1) * 3 + 1], r1);
                r2 = fmaf(b, s[OFF_W5 + (kk + 1) * 3 + 2], r2);
            }
        }
    }

    r0 = 1.0f / (1.0f + expf(-r0));
    r1 = 1.0f / (1.0f + expf(-r1));
    r2 = 1.0f / (1.0f + expf(-r2));

    out[3 * i + 0] = r0;
    out[3 * i + 1] = r1;
    out[3 * i + 2] = r2;
}

extern "C" void kernel_launch(void* const* d_in, const int* in_sizes, int n_in,
                              void* d_out, int out_size)
{
    const float* pos    = (const float*)d_in[0];
    const float* dirv   = (const float*)d_in[1];
    const float* tables = (const float*)d_in[2];
    const float* W1 = (const float*)d_in[3];
    const float* B1 = (const float*)d_in[4];
    const float* W2 = (const float*)d_in[5];
    const float* B2 = (const float*)d_in[6];
    const float* W3 = (const float*)d_in[7];
    const float* B3 = (const float*)d_in[8];
    const float* W4 = (const float*)d_in[9];
    const float* B4 = (const float*)d_in[10];
    const float* W5 = (const float*)d_in[11];
    const float* B5 = (const float*)d_in[12];
    float* out = (float*)d_out;

    nerf_fused_kernel<<<NPTS / 256, 256>>>(
        pos, dirv, tables,
        W1, B1, W2, B2, W3, B3, W4, B4, W5, B5, out);
}